// round 1
// baseline (speedup 1.0000x reference)
#include <cuda_runtime.h>
#include <math.h>

typedef unsigned long long ull;

#define NLAYERS 40
#define TB 256
#define NT 256
#define SMEM_FLOATS (8192 + 12288 + 192 + 16384 + 16384)
#define SMEM_BYTES (SMEM_FLOATS * 4)

// Ping-pong activation buffers (fixed stride 8192 per channel row) + packed weights.
__device__ float g_buf0[8 * 64 * 8192];
__device__ float g_buf1[8 * 64 * 8192];
__device__ float g_wd[NLAYERS * 64 * 128];     // [l][i][ k*64 + o ]  (dilated conv, taps 0/1)
__device__ float g_w2[NLAYERS * 64 * 192];     // [l][i][ o ]  o<64: res, o>=64: skip
__device__ float g_bias[NLAYERS * 192];        // [l][ o ]     o<64: b_res, o>=64: b_skip

// ---- f32x2 helpers (Blackwell packed FP32 pipe; ptxas won't emit FFMA2 from C++) ----
__device__ __forceinline__ ull pkdup(float x) {
    ull r; asm("mov.b64 %0, {%1, %1};" : "=l"(r) : "f"(x)); return r;
}
__device__ __forceinline__ ull pk(float lo, float hi) {
    ull r; asm("mov.b64 %0, {%1, %2};" : "=l"(r) : "f"(lo), "f"(hi)); return r;
}
__device__ __forceinline__ void upk(ull v, float& lo, float& hi) {
    asm("mov.b64 {%0, %1}, %2;" : "=f"(lo), "=f"(hi) : "l"(v));
}
__device__ __forceinline__ void fma2(ull& d, ull a, ull b) {
    asm("fma.rn.f32x2 %0, %1, %2, %0;" : "+l"(d) : "l"(a), "l"(b));
}

// gated = tanh(y) * sigmoid(y), numerically safe, ~1e-6 rel err
__device__ __forceinline__ float gate_fn(float y) {
    float ay = fabsf(y);
    float e1 = __expf(-ay);
    float e2 = e1 * e1;
    float th = __fdividef(1.f - e2, 1.f + e2);   // tanh(|y|)
    float sp = __fdividef(1.f, 1.f + e1);        // sigmoid(|y|)
    float sig = (y >= 0.f) ? sp : (1.f - sp);
    return copysignf(th, y) * sig;
}

// ------------------------- weight repack -------------------------
#define RN1 (NLAYERS * 64 * 64 * 2)
#define RN2 (NLAYERS * 64 * 64)
#define RN3 (NLAYERS * 128 * 64)
#define RN4 (NLAYERS * 64)
#define RN5 (NLAYERS * 128)
#define RNTOT (RN1 + RN2 + RN3 + RN4 + RN5)

__global__ void repack_kernel(const float* __restrict__ wd, const float* __restrict__ wr,
                              const float* __restrict__ br, const float* __restrict__ ws,
                              const float* __restrict__ bs) {
    int idx = blockIdx.x * blockDim.x + threadIdx.x;
    if (idx < RN1) {  // w_dil[l][o][i][k] -> g_wd[l][i][k*64+o]
        int k = idx & 1, i = (idx >> 1) & 63, o = (idx >> 7) & 63, l = idx >> 13;
        g_wd[(l * 64 + i) * 128 + k * 64 + o] = wd[idx];
        return;
    }
    idx -= RN1;
    if (idx < RN2) {  // w_res[l][o][i] -> g_w2[l][i][o]
        int i = idx & 63, o = (idx >> 6) & 63, l = idx >> 12;
        g_w2[(l * 64 + i) * 192 + o] = wr[idx];
        return;
    }
    idx -= RN2;
    if (idx < RN3) {  // w_skip[l][o][i] -> g_w2[l][i][64+o]
        int i = idx & 63, o = (idx >> 6) & 127, l = idx >> 13;
        g_w2[(l * 64 + i) * 192 + 64 + o] = ws[idx];
        return;
    }
    idx -= RN3;
    if (idx < RN4) { int o = idx & 63, l = idx >> 6; g_bias[l * 192 + o] = br[idx]; return; }
    idx -= RN4;
    if (idx < RN5) { int o = idx & 127, l = idx >> 7; g_bias[l * 192 + 64 + o] = bs[idx]; return; }
}

// ------------------------- fused layer kernel -------------------------
// CTA: one batch b, 256 output timesteps [t0, t0+256).
// phase1: y[64 x 256] = W0 @ x[t] + W1 @ x[t+d]  -> gated (into SMEM, reusing xa)
// phase2: res = Wr @ gated + b_res + x[t+d]  -> dst
// phase3: skip = Wsk @ gated + b_skip        -> out (last 4096 only)
__global__ __launch_bounds__(NT, 1) void layer_kernel(
    const float* __restrict__ src, float* __restrict__ dst,
    const float* __restrict__ wd, const float* __restrict__ w2,
    const float* __restrict__ bias, float* __restrict__ skipOut,
    int d, int L) {
    extern __shared__ float smem[];
    float* sW1 = smem;                 // 64 x 128
    float* sW2 = smem + 8192;          // 64 x 192
    float* sBias = smem + 20480;       // 192
    float* sXa = smem + 20672;         // 64 x 256  (reused as gated)
    float* sXb = smem + 37056;         // 64 x 256

    const int tid = threadIdx.x;
    const int b = blockIdx.y;
    const int t0 = blockIdx.x * TB;
    const int T = L + d;

    // --- load weights (float4, broadcast-friendly) ---
    {
        const float4* g4 = (const float4*)wd;
        float4* s4 = (float4*)sW1;
        for (int i = tid; i < 2048; i += NT) s4[i] = g4[i];
        g4 = (const float4*)w2;
        s4 = (float4*)sW2;
        for (int i = tid; i < 3072; i += NT) s4[i] = g4[i];
        if (tid < 192) sBias[tid] = bias[tid];
    }
    // --- load activation tiles (clamped tail) ---
    const float* srcB = src + (size_t)b * 64 * 8192;
    for (int idx = tid; idx < 64 * TB; idx += NT) {
        int i = idx >> 8;
        int t = idx & 255;
        int ta = t0 + t; if (ta > T - 1) ta = T - 1;
        int tb = t0 + t + d; if (tb > T - 1) tb = T - 1;
        const float* row = srcB + i * 8192;
        sXa[idx] = row[ta];
        sXb[idx] = row[tb];
    }
    __syncthreads();

    const int tg = tid & 31;   // lane: pair-group base (pairs p = tg + 32*j)
    const int og = tid >> 5;   // warp: 8 output channels og*8..og*8+7
    const ull* xa2 = (const ull*)sXa;
    const ull* xb2 = (const ull*)sXb;

    // ---------------- phase 1: dilated conv GEMM ----------------
    ull acc[8][4];
#pragma unroll
    for (int c = 0; c < 8; c++)
#pragma unroll
        for (int j = 0; j < 4; j++) acc[c][j] = 0ull;

#pragma unroll 2
    for (int i = 0; i < 64; i++) {
        const ull* xaRow = xa2 + i * 128 + tg;
        const ull* xbRow = xb2 + i * 128 + tg;
        ull a0 = xaRow[0], a1 = xaRow[32], a2 = xaRow[64], a3 = xaRow[96];
        ull b0 = xbRow[0], b1 = xbRow[32], b2 = xbRow[64], b3 = xbRow[96];
        const float* wbase = sW1 + i * 128 + (og << 3);
        float4 wa0 = *(const float4*)(wbase);
        float4 wa1 = *(const float4*)(wbase + 4);
        float4 wb0 = *(const float4*)(wbase + 64);
        float4 wb1 = *(const float4*)(wbase + 68);
        float w0[8] = {wa0.x, wa0.y, wa0.z, wa0.w, wa1.x, wa1.y, wa1.z, wa1.w};
        float w1[8] = {wb0.x, wb0.y, wb0.z, wb0.w, wb1.x, wb1.y, wb1.z, wb1.w};
#pragma unroll
        for (int c = 0; c < 8; c++) {
            ull p0 = pkdup(w0[c]);
            fma2(acc[c][0], p0, a0); fma2(acc[c][1], p0, a1);
            fma2(acc[c][2], p0, a2); fma2(acc[c][3], p0, a3);
            ull p1 = pkdup(w1[c]);
            fma2(acc[c][0], p1, b0); fma2(acc[c][1], p1, b1);
            fma2(acc[c][2], p1, b2); fma2(acc[c][3], p1, b3);
        }
    }
    __syncthreads();

    // gated -> SMEM (reuse sXa)
    ull* sG2 = (ull*)sXa;
#pragma unroll
    for (int c = 0; c < 8; c++) {
        int o = (og << 3) + c;
#pragma unroll
        for (int j = 0; j < 4; j++) {
            float y0, y1;
            upk(acc[c][j], y0, y1);
            sG2[o * 128 + tg + 32 * j] = pk(gate_fn(y0), gate_fn(y1));
        }
    }
    __syncthreads();

    // ---------------- phase 2/3: res + skip GEMMs ----------------
    const int skipOff = L - 4096;
    const bool needSkip = (t0 + TB > skipOff);
    const bool fullTile = (t0 + TB <= L);
    const int nb = needSkip ? 3 : 1;

    for (int cb = 0; cb < nb; cb++) {
        ull a2c[8][4];
#pragma unroll
        for (int c = 0; c < 8; c++)
#pragma unroll
            for (int j = 0; j < 4; j++) a2c[c][j] = 0ull;

#pragma unroll 2
        for (int i = 0; i < 64; i++) {
            const ull* gRow = sG2 + i * 128 + tg;
            ull g0 = gRow[0], g1 = gRow[32], g2 = gRow[64], g3 = gRow[96];
            const float* wbase = sW2 + i * 192 + cb * 64 + (og << 3);
            float4 wa = *(const float4*)(wbase);
            float4 wb = *(const float4*)(wbase + 4);
            float w[8] = {wa.x, wa.y, wa.z, wa.w, wb.x, wb.y, wb.z, wb.w};
#pragma unroll
            for (int c = 0; c < 8; c++) {
                ull p = pkdup(w[c]);
                fma2(a2c[c][0], p, g0); fma2(a2c[c][1], p, g1);
                fma2(a2c[c][2], p, g2); fma2(a2c[c][3], p, g3);
            }
        }

        if (cb == 0) {
            // residual: dst[b][o][t0+t] = acc + b_res[o] + x[t+d]
#pragma unroll
            for (int c = 0; c < 8; c++) {
                int o = (og << 3) + c;
                float bo = sBias[o];
                float* drow = dst + (size_t)(b * 64 + o) * 8192;
#pragma unroll
                for (int j = 0; j < 4; j++) {
                    int p = tg + 32 * j;
                    int gt = t0 + 2 * p;
                    float v0, v1, x0, x1;
                    upk(a2c[c][j], v0, v1);
                    upk(xb2[o * 128 + p], x0, x1);
                    v0 += bo + x0;
                    v1 += bo + x1;
                    if (fullTile) {
                        *(float2*)(drow + gt) = make_float2(v0, v1);
                    } else {
                        if (gt < L) drow[gt] = v0;
                        if (gt + 1 < L) drow[gt + 1] = v1;
                    }
                }
            }
        } else {
            // skip: out[l][b][o][s], s = t - skipOff
            const bool fullSkip = fullTile && (t0 >= skipOff);
#pragma unroll
            for (int c = 0; c < 8; c++) {
                int oc = cb * 64 + (og << 3) + c;   // 64..191
                float bo = sBias[oc];
                int o = oc - 64;                    // 0..127
                float* srow = skipOut + ((size_t)b * 128 + o) * 4096;
#pragma unroll
                for (int j = 0; j < 4; j++) {
                    int p = tg + 32 * j;
                    int gt = t0 + 2 * p;
                    int s0 = gt - skipOff;
                    float v0, v1;
                    upk(a2c[c][j], v0, v1);
                    v0 += bo;
                    v1 += bo;
                    if (fullSkip) {
                        srow[s0] = v0;
                        srow[s0 + 1] = v1;
                    } else {
                        if (s0 >= 0 && gt < L) srow[s0] = v0;
                        if (s0 + 1 >= 0 && gt + 1 < L) srow[s0 + 1] = v1;
                    }
                }
            }
        }
    }
}

// ------------------------- launch -------------------------
extern "C" void kernel_launch(void* const* d_in, const int* in_sizes, int n_in,
                              void* d_out, int out_size) {
    const float* x      = (const float*)d_in[0];
    const float* w_dil  = (const float*)d_in[1];
    const float* w_res  = (const float*)d_in[2];
    const float* b_res  = (const float*)d_in[3];
    const float* w_skip = (const float*)d_in[4];
    const float* b_skip = (const float*)d_in[5];
    float* out = (float*)d_out;
    (void)in_sizes; (void)n_in; (void)out_size;

    cudaFuncSetAttribute(layer_kernel, cudaFuncAttributeMaxDynamicSharedMemorySize, SMEM_BYTES);

    float *bufA, *bufB, *wdP, *w2P, *biasP;
    cudaGetSymbolAddress((void**)&bufA, g_buf0);
    cudaGetSymbolAddress((void**)&bufB, g_buf1);
    cudaGetSymbolAddress((void**)&wdP, g_wd);
    cudaGetSymbolAddress((void**)&w2P, g_w2);
    cudaGetSymbolAddress((void**)&biasP, g_bias);

    repack_kernel<<<(RNTOT + 255) / 256, 256>>>(w_dil, w_res, b_res, w_skip, b_skip);

    int T = 8192;
    const float* src = x;
    for (int l = 0; l < NLAYERS; l++) {
        int d = 1 << (l % 10);
        int L = T - d;
        float* dst = (l & 1) ? bufB : bufA;
        dim3 grid((L + TB - 1) / TB, 8);
        layer_kernel<<<grid, NT, SMEM_BYTES>>>(
            src, dst,
            wdP + (size_t)l * 8192, w2P + (size_t)l * 12288, biasP + (size_t)l * 192,
            out + (size_t)l * 8 * 128 * 4096, d, L);
        src = dst;
        T = L;
    }
}

// round 2
// speedup vs baseline: 1.0514x; 1.0514x over previous
#include <cuda_runtime.h>
#include <math.h>

typedef unsigned long long ull;

#define NLAYERS 40
#define TB 192
#define NPAIR 96          // TB/2
#define NT 256
#define SMEM_FLOATS (64 * TB * 2 + 192)
#define SMEM_BYTES (SMEM_FLOATS * 4)

// Ping-pong activation buffers (stride 8192 per channel row) + packed weights.
__device__ float g_buf0[8 * 64 * 8192];
__device__ float g_buf1[8 * 64 * 8192];
__device__ float g_wd[NLAYERS * 64 * 128];     // [l][i][k*64 + o]
__device__ float g_w2[NLAYERS * 64 * 192];     // [l][i][o]  o<64: res, o>=64: skip
__device__ float g_bias[NLAYERS * 192];

// ---- f32x2 helpers (packed FP32 pipe; ptxas won't emit FFMA2 from C++) ----
__device__ __forceinline__ ull pkdup(float x) {
    ull r; asm("mov.b64 %0, {%1, %1};" : "=l"(r) : "f"(x)); return r;
}
__device__ __forceinline__ ull pk(float lo, float hi) {
    ull r; asm("mov.b64 %0, {%1, %2};" : "=l"(r) : "f"(lo), "f"(hi)); return r;
}
__device__ __forceinline__ void upk(ull v, float& lo, float& hi) {
    asm("mov.b64 {%0, %1}, %2;" : "=f"(lo), "=f"(hi) : "l"(v));
}
__device__ __forceinline__ void fma2(ull& d, ull a, ull b) {
    asm("fma.rn.f32x2 %0, %1, %2, %0;" : "+l"(d) : "l"(a), "l"(b));
}

__device__ __forceinline__ float gate_fn(float y) {
    float ay = fabsf(y);
    float e1 = __expf(-ay);
    float e2 = e1 * e1;
    float th = __fdividef(1.f - e2, 1.f + e2);
    float sp = __fdividef(1.f, 1.f + e1);
    float sig = (y >= 0.f) ? sp : (1.f - sp);
    return copysignf(th, y) * sig;
}

// ------------------------- weight repack -------------------------
#define RN1 (NLAYERS * 64 * 64 * 2)
#define RN2 (NLAYERS * 64 * 64)
#define RN3 (NLAYERS * 128 * 64)
#define RN4 (NLAYERS * 64)
#define RN5 (NLAYERS * 128)
#define RNTOT (RN1 + RN2 + RN3 + RN4 + RN5)

__global__ void repack_kernel(const float* __restrict__ wd, const float* __restrict__ wr,
                              const float* __restrict__ br, const float* __restrict__ ws,
                              const float* __restrict__ bs) {
    int idx = blockIdx.x * blockDim.x + threadIdx.x;
    if (idx < RN1) {
        int k = idx & 1, i = (idx >> 1) & 63, o = (idx >> 7) & 63, l = idx >> 13;
        g_wd[(l * 64 + i) * 128 + k * 64 + o] = wd[idx];
        return;
    }
    idx -= RN1;
    if (idx < RN2) {
        int i = idx & 63, o = (idx >> 6) & 63, l = idx >> 12;
        g_w2[(l * 64 + i) * 192 + o] = wr[idx];
        return;
    }
    idx -= RN2;
    if (idx < RN3) {
        int i = idx & 63, o = (idx >> 6) & 127, l = idx >> 13;
        g_w2[(l * 64 + i) * 192 + 64 + o] = ws[idx];
        return;
    }
    idx -= RN3;
    if (idx < RN4) { int o = idx & 63, l = idx >> 6; g_bias[l * 192 + o] = br[idx]; return; }
    idx -= RN4;
    if (idx < RN5) { int o = idx & 127, l = idx >> 7; g_bias[l * 192 + 64 + o] = bs[idx]; return; }
}

// ------------------------- fused layer kernel -------------------------
// Right-aligned time tiles: tile k covers [L - (nTiles-k)*TB, ...). Only tile 0 ragged.
// Weights come from gmem via warp-uniform __ldg (L1 broadcast) — smem holds only x/gated.
__global__ __launch_bounds__(NT, 2) void layer_kernel(
    const float* __restrict__ src, int srcOff,
    float* __restrict__ dst, int dstOff,
    const float* __restrict__ wd, const float* __restrict__ w2,
    const float* __restrict__ bias, float* __restrict__ skipOut,
    int d, int L, int nTiles) {
    extern __shared__ float smem[];
    float* sXa = smem;                     // 64 x 192 (reused as gated)
    float* sXb = smem + 64 * TB;           // 64 x 192
    float* sBias = smem + 64 * TB * 2;     // 192

    const int tid = threadIdx.x;
    const int b = blockIdx.y;
    const int t0 = L - (nTiles - blockIdx.x) * TB;
    const int Tin = L + d;

    if (tid < 192) sBias[tid] = bias[tid];

    // --- stage activation windows (clamped at edges) ---
    const float* srcB = src + (size_t)b * 64 * 8192 + srcOff;
    for (int idx = tid; idx < 64 * TB; idx += NT) {
        int i = idx / TB;
        int t = idx - i * TB;
        int ga = t0 + t;     ga = min(max(ga, 0), Tin - 1);
        int gb = t0 + t + d; gb = min(max(gb, 0), Tin - 1);
        const float* row = srcB + i * 8192;
        sXa[idx] = row[ga];
        sXb[idx] = row[gb];
    }
    __syncthreads();

    const int tg = tid & 31;   // lane -> pairs p = tg + 32*j, j<3
    const int og = tid >> 5;   // warp -> channels og*8 .. og*8+7
    const ull* xa2 = (const ull*)sXa;
    const ull* xb2 = (const ull*)sXb;

    // ---------------- phase 1: dilated conv GEMM ----------------
    ull acc[8][3];
#pragma unroll
    for (int c = 0; c < 8; c++)
#pragma unroll
        for (int j = 0; j < 3; j++) acc[c][j] = 0ull;

    const float4* wd4 = (const float4*)wd;   // row i: 32 float4
#pragma unroll 2
    for (int i = 0; i < 64; i++) {
        const ull* xaRow = xa2 + i * NPAIR + tg;
        const ull* xbRow = xb2 + i * NPAIR + tg;
        ull a0 = xaRow[0], a1 = xaRow[32], a2 = xaRow[64];
        ull b0 = xbRow[0], b1 = xbRow[32], b2 = xbRow[64];
        float4 wa0 = __ldg(wd4 + i * 32 + og * 2);
        float4 wa1 = __ldg(wd4 + i * 32 + og * 2 + 1);
        float4 wb0 = __ldg(wd4 + i * 32 + 16 + og * 2);
        float4 wb1 = __ldg(wd4 + i * 32 + 16 + og * 2 + 1);
        float w0[8] = {wa0.x, wa0.y, wa0.z, wa0.w, wa1.x, wa1.y, wa1.z, wa1.w};
        float w1[8] = {wb0.x, wb0.y, wb0.z, wb0.w, wb1.x, wb1.y, wb1.z, wb1.w};
#pragma unroll
        for (int c = 0; c < 8; c++) {
            ull p0 = pkdup(w0[c]);
            fma2(acc[c][0], p0, a0); fma2(acc[c][1], p0, a1); fma2(acc[c][2], p0, a2);
            ull p1 = pkdup(w1[c]);
            fma2(acc[c][0], p1, b0); fma2(acc[c][1], p1, b1); fma2(acc[c][2], p1, b2);
        }
    }
    __syncthreads();   // everyone done reading sXa before we overwrite with gated

    ull* sG2 = (ull*)sXa;
#pragma unroll
    for (int c = 0; c < 8; c++) {
        int o = (og << 3) + c;
#pragma unroll
        for (int j = 0; j < 3; j++) {
            float y0, y1;
            upk(acc[c][j], y0, y1);
            sG2[o * NPAIR + tg + 32 * j] = pk(gate_fn(y0), gate_fn(y1));
        }
    }
    __syncthreads();

    // ---------------- phase 2/3: res + skip GEMMs ----------------
    const int skipOff = L - 4096;
    const bool needSkip = (t0 + TB > skipOff);
    const bool fullTile = (t0 >= 0);
    const bool fullSkip = (t0 >= skipOff);
    const int nb = needSkip ? 3 : 1;
    const float4* w24 = (const float4*)w2;   // row i: 48 float4

    for (int cb = 0; cb < nb; cb++) {
        ull a2c[8][3];
#pragma unroll
        for (int c = 0; c < 8; c++)
#pragma unroll
            for (int j = 0; j < 3; j++) a2c[c][j] = 0ull;

#pragma unroll 2
        for (int i = 0; i < 64; i++) {
            const ull* gRow = sG2 + i * NPAIR + tg;
            ull g0 = gRow[0], g1 = gRow[32], g2 = gRow[64];
            float4 wa = __ldg(w24 + i * 48 + cb * 16 + og * 2);
            float4 wb = __ldg(w24 + i * 48 + cb * 16 + og * 2 + 1);
            float w[8] = {wa.x, wa.y, wa.z, wa.w, wb.x, wb.y, wb.z, wb.w};
#pragma unroll
            for (int c = 0; c < 8; c++) {
                ull p = pkdup(w[c]);
                fma2(a2c[c][0], p, g0); fma2(a2c[c][1], p, g1); fma2(a2c[c][2], p, g2);
            }
        }

        if (cb == 0) {
            // residual: dst[(b,o)][gt + dstOff] = acc + b_res + x[t+d]
#pragma unroll
            for (int c = 0; c < 8; c++) {
                int o = (og << 3) + c;
                float bo = sBias[o];
                float* drow = dst + (size_t)(b * 64 + o) * 8192 + dstOff;
#pragma unroll
                for (int j = 0; j < 3; j++) {
                    int p = tg + 32 * j;
                    int gt = t0 + 2 * p;
                    float v0, v1, x0, x1;
                    upk(a2c[c][j], v0, v1);
                    upk(xb2[o * NPAIR + p], x0, x1);
                    v0 += bo + x0;
                    v1 += bo + x1;
                    if (fullTile) {
                        *(float2*)(drow + gt) = make_float2(v0, v1);   // (gt+dstOff) even
                    } else {
                        if (gt >= 0) *(float2*)(drow + gt) = make_float2(v0, v1);
                        else if (gt == -1) drow[gt + 1] = v1;
                    }
                }
            }
        } else {
            // skip: out[(l,b,o)][s], s = gt - skipOff (always even -> aligned float2)
#pragma unroll
            for (int c = 0; c < 8; c++) {
                int oc = cb * 64 + (og << 3) + c;
                float bo = sBias[oc];
                float* srow = skipOut + ((size_t)b * 128 + (oc - 64)) * 4096;
#pragma unroll
                for (int j = 0; j < 3; j++) {
                    int p = tg + 32 * j;
                    int s0 = t0 + 2 * p - skipOff;
                    float v0, v1;
                    upk(a2c[c][j], v0, v1);
                    v0 += bo;
                    v1 += bo;
                    if (fullSkip) {
                        *(float2*)(srow + s0) = make_float2(v0, v1);
                    } else if (s0 >= 0) {
                        *(float2*)(srow + s0) = make_float2(v0, v1);
                    }
                }
            }
        }
    }
}

// ------------------------- launch -------------------------
extern "C" void kernel_launch(void* const* d_in, const int* in_sizes, int n_in,
                              void* d_out, int out_size) {
    const float* x      = (const float*)d_in[0];
    const float* w_dil  = (const float*)d_in[1];
    const float* w_res  = (const float*)d_in[2];
    const float* b_res  = (const float*)d_in[3];
    const float* w_skip = (const float*)d_in[4];
    const float* b_skip = (const float*)d_in[5];
    float* out = (float*)d_out;
    (void)in_sizes; (void)n_in; (void)out_size;

    cudaFuncSetAttribute(layer_kernel, cudaFuncAttributeMaxDynamicSharedMemorySize, SMEM_BYTES);

    float *bufA, *bufB, *wdP, *w2P, *biasP;
    cudaGetSymbolAddress((void**)&bufA, g_buf0);
    cudaGetSymbolAddress((void**)&bufB, g_buf1);
    cudaGetSymbolAddress((void**)&wdP, g_wd);
    cudaGetSymbolAddress((void**)&w2P, g_w2);
    cudaGetSymbolAddress((void**)&biasP, g_bias);

    repack_kernel<<<(RNTOT + 255) / 256, 256>>>(w_dil, w_res, b_res, w_skip, b_skip);

    int T = 8192;
    const float* src = x;
    int srcOff = 0;
    for (int l = 0; l < NLAYERS; l++) {
        int d = 1 << (l % 10);
        int L = T - d;
        int dstOff = L & 1;   // store parity fix so float2 stores stay 8B-aligned
        float* dst = (l & 1) ? bufB : bufA;
        int nTiles = (L + TB - 1) / TB;
        dim3 grid(nTiles, 8);
        layer_kernel<<<grid, NT, SMEM_BYTES>>>(
            src, srcOff, dst, dstOff,
            wdP + (size_t)l * 8192, w2P + (size_t)l * 12288, biasP + (size_t)l * 192,
            out + (size_t)l * 8 * 128 * 4096, d, L, nTiles);
        src = dst;
        srcOff = dstOff;
        T = L;
    }
}

// round 3
// speedup vs baseline: 1.4679x; 1.3962x over previous
#include <cuda_runtime.h>
#include <math.h>

typedef unsigned long long ull;

#define NLAYERS 40
#define TB 128
#define NPAIR 64          // TB/2
#define NT 256
// smem: weight region 8192 floats (32KB) + sXa 8192 + sXb 8192 + bias 192
#define SMEM_FLOATS (8192 + 8192 + 8192 + 192)
#define SMEM_BYTES (SMEM_FLOATS * 4)

__device__ float g_buf0[8 * 64 * 8192];
__device__ float g_buf1[8 * 64 * 8192];
__device__ float g_wd[NLAYERS * 64 * 128];     // [l][i][k*64 + o]
__device__ float g_w2[NLAYERS * 64 * 192];     // [l][i][o]  o<64: res, o>=64: skip
__device__ float g_bias[NLAYERS * 192];

// ---- f32x2 helpers ----
__device__ __forceinline__ ull pkdup(float x) {
    ull r; asm("mov.b64 %0, {%1, %1};" : "=l"(r) : "f"(x)); return r;
}
__device__ __forceinline__ ull pk(float lo, float hi) {
    ull r; asm("mov.b64 %0, {%1, %2};" : "=l"(r) : "f"(lo), "f"(hi)); return r;
}
__device__ __forceinline__ void upk(ull v, float& lo, float& hi) {
    asm("mov.b64 {%0, %1}, %2;" : "=f"(lo), "=f"(hi) : "l"(v));
}
__device__ __forceinline__ void fma2(ull& d, ull a, ull b) {
    asm("fma.rn.f32x2 %0, %1, %2, %0;" : "+l"(d) : "l"(a), "l"(b));
}

__device__ __forceinline__ float gate_fn(float y) {
    float ay = fabsf(y);
    float e1 = __expf(-ay);
    float e2 = e1 * e1;
    float th = __fdividef(1.f - e2, 1.f + e2);
    float sp = __fdividef(1.f, 1.f + e1);
    float sig = (y >= 0.f) ? sp : (1.f - sp);
    return copysignf(th, y) * sig;
}

// ------------------------- weight repack -------------------------
#define RN1 (NLAYERS * 64 * 64 * 2)
#define RN2 (NLAYERS * 64 * 64)
#define RN3 (NLAYERS * 128 * 64)
#define RN4 (NLAYERS * 64)
#define RN5 (NLAYERS * 128)
#define RNTOT (RN1 + RN2 + RN3 + RN4 + RN5)

__global__ void repack_kernel(const float* __restrict__ wd, const float* __restrict__ wr,
                              const float* __restrict__ br, const float* __restrict__ ws,
                              const float* __restrict__ bs) {
    int idx = blockIdx.x * blockDim.x + threadIdx.x;
    if (idx < RN1) {
        int k = idx & 1, i = (idx >> 1) & 63, o = (idx >> 7) & 63, l = idx >> 13;
        g_wd[(l * 64 + i) * 128 + k * 64 + o] = wd[idx];
        return;
    }
    idx -= RN1;
    if (idx < RN2) {
        int i = idx & 63, o = (idx >> 6) & 63, l = idx >> 12;
        g_w2[(l * 64 + i) * 192 + o] = wr[idx];
        return;
    }
    idx -= RN2;
    if (idx < RN3) {
        int i = idx & 63, o = (idx >> 6) & 127, l = idx >> 13;
        g_w2[(l * 64 + i) * 192 + 64 + o] = ws[idx];
        return;
    }
    idx -= RN3;
    if (idx < RN4) { int o = idx & 63, l = idx >> 6; g_bias[l * 192 + o] = br[idx]; return; }
    idx -= RN4;
    if (idx < RN5) { int o = idx & 127, l = idx >> 7; g_bias[l * 192 + 64 + o] = bs[idx]; return; }
}

// ------------------------- fused layer kernel -------------------------
// Right-aligned tiles of TB timesteps; only tile 0 ragged.
// All hot-loop operands come from SMEM (broadcast LDS for weights).
// Weight region (32KB) staged per phase: wd for phase1, then 16KB column
// blocks of w2 per cb pass.
__global__ __launch_bounds__(NT, 2) void layer_kernel(
    const float* __restrict__ src, int srcOff,
    float* __restrict__ dst, int dstOff,
    const float* __restrict__ wd, const float* __restrict__ w2,
    const float* __restrict__ bias, float* __restrict__ skipOut,
    int d, int L, int nTiles) {
    extern __shared__ float smem[];
    float* sW = smem;                       // 8192 floats (weight stage)
    float* sXa = smem + 8192;               // 64 x 128 (reused as gated)
    float* sXb = smem + 16384;              // 64 x 128
    float* sBias = smem + 24576;            // 192

    const int tid = threadIdx.x;
    const int b = blockIdx.y;
    const int t0 = L - (nTiles - blockIdx.x) * TB;
    const int Tin = L + d;

    if (tid < 192) sBias[tid] = bias[tid];

    // stage wd (8192 floats, contiguous float4)
    {
        const float4* g4 = (const float4*)wd;
        float4* s4 = (float4*)sW;
#pragma unroll
        for (int k = 0; k < 8; k++) s4[tid + NT * k] = g4[tid + NT * k];
    }
    // stage activation windows (clamped at edges)
    const float* srcB = src + (size_t)b * 64 * 8192 + srcOff;
    for (int idx = tid; idx < 64 * TB; idx += NT) {
        int i = idx >> 7;
        int t = idx & 127;
        int ga = t0 + t;     ga = min(max(ga, 0), Tin - 1);
        int gb = t0 + t + d; gb = min(max(gb, 0), Tin - 1);
        const float* row = srcB + i * 8192;
        sXa[idx] = row[ga];
        sXb[idx] = row[gb];
    }
    __syncthreads();

    const int tg = tid & 31;   // lane -> pairs p = tg + 32*j, j<2
    const int og = tid >> 5;   // warp -> channels og*8 .. og*8+7
    const ull* xa2 = (const ull*)sXa;
    const ull* xb2 = (const ull*)sXb;

    // ---------------- phase 1: dilated conv GEMM ----------------
    ull acc[8][2];
#pragma unroll
    for (int c = 0; c < 8; c++) { acc[c][0] = 0ull; acc[c][1] = 0ull; }

#pragma unroll 4
    for (int i = 0; i < 64; i++) {
        const ull* xaRow = xa2 + i * NPAIR + tg;
        const ull* xbRow = xb2 + i * NPAIR + tg;
        ull a0 = xaRow[0], a1 = xaRow[32];
        ull b0 = xbRow[0], b1 = xbRow[32];
        const float* wbase = sW + i * 128 + (og << 3);
        float4 wa0 = *(const float4*)(wbase);
        float4 wa1 = *(const float4*)(wbase + 4);
        float4 wb0 = *(const float4*)(wbase + 64);
        float4 wb1 = *(const float4*)(wbase + 68);
        float w0[8] = {wa0.x, wa0.y, wa0.z, wa0.w, wa1.x, wa1.y, wa1.z, wa1.w};
        float w1[8] = {wb0.x, wb0.y, wb0.z, wb0.w, wb1.x, wb1.y, wb1.z, wb1.w};
#pragma unroll
        for (int c = 0; c < 8; c++) {
            ull p0 = pkdup(w0[c]);
            fma2(acc[c][0], p0, a0); fma2(acc[c][1], p0, a1);
            ull p1 = pkdup(w1[c]);
            fma2(acc[c][0], p1, b0); fma2(acc[c][1], p1, b1);
        }
    }
    __syncthreads();   // phase1 reads of sW / sXa complete

    // gated -> sXa; stage w2 column-block 0 (res weights) -> sW
    ull* sG2 = (ull*)sXa;
#pragma unroll
    for (int c = 0; c < 8; c++) {
        int o = (og << 3) + c;
#pragma unroll
        for (int j = 0; j < 2; j++) {
            float y0, y1;
            upk(acc[c][j], y0, y1);
            sG2[o * NPAIR + tg + 32 * j] = pk(gate_fn(y0), gate_fn(y1));
        }
    }
    {
        // 4096 floats = 1024 float4; row i holds 16 float4 of block cb=0
        const float4* g4 = (const float4*)w2;
        float4* s4 = (float4*)sW;
#pragma unroll
        for (int k = 0; k < 4; k++) {
            int idx = tid + NT * k;
            int row = idx >> 4, c4 = idx & 15;
            s4[idx] = g4[row * 48 + c4];
        }
    }
    __syncthreads();

    // ---------------- phase 2/3: res + skip GEMMs ----------------
    const int skipOff = L - 4096;
    const bool needSkip = (t0 + TB > skipOff);
    const bool fullTile = (t0 >= 0);
    const bool fullSkip = (t0 >= skipOff);
    const int nb = needSkip ? 3 : 1;

    for (int cb = 0; cb < nb; cb++) {
        ull a2c[8][2];
#pragma unroll
        for (int c = 0; c < 8; c++) { a2c[c][0] = 0ull; a2c[c][1] = 0ull; }

#pragma unroll 4
        for (int i = 0; i < 64; i++) {
            const ull* gRow = sG2 + i * NPAIR + tg;
            ull g0 = gRow[0], g1 = gRow[32];
            const float* wbase = sW + i * 64 + (og << 3);
            float4 wa = *(const float4*)(wbase);
            float4 wb = *(const float4*)(wbase + 4);
            float w[8] = {wa.x, wa.y, wa.z, wa.w, wb.x, wb.y, wb.z, wb.w};
#pragma unroll
            for (int c = 0; c < 8; c++) {
                ull p = pkdup(w[c]);
                fma2(a2c[c][0], p, g0); fma2(a2c[c][1], p, g1);
            }
        }

        if (cb == 0) {
#pragma unroll
            for (int c = 0; c < 8; c++) {
                int o = (og << 3) + c;
                float bo = sBias[o];
                float* drow = dst + (size_t)(b * 64 + o) * 8192 + dstOff;
#pragma unroll
                for (int j = 0; j < 2; j++) {
                    int p = tg + 32 * j;
                    int gt = t0 + 2 * p;
                    float v0, v1, x0, x1;
                    upk(a2c[c][j], v0, v1);
                    upk(xb2[o * NPAIR + p], x0, x1);
                    v0 += bo + x0;
                    v1 += bo + x1;
                    if (fullTile) {
                        *(float2*)(drow + gt) = make_float2(v0, v1);
                    } else {
                        if (gt >= 0) *(float2*)(drow + gt) = make_float2(v0, v1);
                        else if (gt == -1) drow[gt + 1] = v1;
                    }
                }
            }
        } else {
#pragma unroll
            for (int c = 0; c < 8; c++) {
                int oc = cb * 64 + (og << 3) + c;
                float bo = sBias[oc];
                float* srow = skipOut + ((size_t)b * 128 + (oc - 64)) * 4096;
#pragma unroll
                for (int j = 0; j < 2; j++) {
                    int p = tg + 32 * j;
                    int s0 = t0 + 2 * p - skipOff;
                    float v0, v1;
                    upk(a2c[c][j], v0, v1);
                    v0 += bo;
                    v1 += bo;
                    if (fullSkip || s0 >= 0) {
                        *(float2*)(srow + s0) = make_float2(v0, v1);
                    }
                }
            }
        }

        if (cb + 1 < nb) {
            __syncthreads();   // done reading sW for this cb
            const float4* g4 = (const float4*)w2;
            float4* s4 = (float4*)sW;
            int coff = (cb + 1) * 16;
#pragma unroll
            for (int k = 0; k < 4; k++) {
                int idx = tid + NT * k;
                int row = idx >> 4, c4 = idx & 15;
                s4[idx] = g4[row * 48 + coff + c4];
            }
            __syncthreads();
        }
    }
}

// ------------------------- launch -------------------------
extern "C" void kernel_launch(void* const* d_in, const int* in_sizes, int n_in,
                              void* d_out, int out_size) {
    const float* x      = (const float*)d_in[0];
    const float* w_dil  = (const float*)d_in[1];
    const float* w_res  = (const float*)d_in[2];
    const float* b_res  = (const float*)d_in[3];
    const float* w_skip = (const float*)d_in[4];
    const float* b_skip = (const float*)d_in[5];
    float* out = (float*)d_out;
    (void)in_sizes; (void)n_in; (void)out_size;

    cudaFuncSetAttribute(layer_kernel, cudaFuncAttributeMaxDynamicSharedMemorySize, SMEM_BYTES);

    float *bufA, *bufB, *wdP, *w2P, *biasP;
    cudaGetSymbolAddress((void**)&bufA, g_buf0);
    cudaGetSymbolAddress((void**)&bufB, g_buf1);
    cudaGetSymbolAddress((void**)&wdP, g_wd);
    cudaGetSymbolAddress((void**)&w2P, g_w2);
    cudaGetSymbolAddress((void**)&biasP, g_bias);

    repack_kernel<<<(RNTOT + 255) / 256, 256>>>(w_dil, w_res, b_res, w_skip, b_skip);

    int T = 8192;
    const float* src = x;
    int srcOff = 0;
    for (int l = 0; l < NLAYERS; l++) {
        int d = 1 << (l % 10);
        int L = T - d;
        int dstOff = L & 1;
        float* dst = (l & 1) ? bufB : bufA;
        int nTiles = (L + TB - 1) / TB;
        dim3 grid(nTiles, 8);
        layer_kernel<<<grid, NT, SMEM_BYTES>>>(
            src, srcOff, dst, dstOff,
            wdP + (size_t)l * 8192, w2P + (size_t)l * 12288, biasP + (size_t)l * 192,
            out + (size_t)l * 8 * 128 * 4096, d, L, nTiles);
        src = dst;
        srcOff = dstOff;
        T = L;
    }
}